// round 1
// baseline (speedup 1.0000x reference)
#include <cuda_runtime.h>
#include <cstdint>

#define N_NODES 100000
#define N_EDGES 1600000
#define IN_F   48
#define EDGE_F 32
#define HID_F  128
#define OUT_F  64

// ---------------- scratch (device globals; allocation-free) ----------------
// float4-typed to guarantee 16B alignment.
__device__ float4 g_h[N_NODES * 24];     // [N,96]  = [nfeat | h_neigh0]
__device__ float4 g_hn1[N_NODES * 24];   // [N,96]  accum of h[src] per dst
__device__ float4 g_h1[N_NODES * 32];    // [N,128]
__device__ float4 g_hn2[N_NODES * 32];   // [N,128] accum of h1[src] per dst
__device__ float  g_deg[N_NODES];
__device__ float  g_inv[N_NODES];

// ---------------- vector reductions ----------------
__device__ __forceinline__ void red_add4(float* p, float4 v) {
    asm volatile("red.global.add.v4.f32 [%0], {%1,%2,%3,%4};"
                 :: "l"(p), "f"(v.x), "f"(v.y), "f"(v.z), "f"(v.w) : "memory");
}
__device__ __forceinline__ void red_add1(float* p, float v) {
    asm volatile("red.global.add.f32 [%0], %1;" :: "l"(p), "f"(v) : "memory");
}

// ---------------- init: build h left half, zero accumulators ----------------
// sections: [0, N*96) h ; [N*96, 2*N*96) hn1 ; [.., +N*128) hn2 ; [.., +N) deg
__global__ void k_init(const float* __restrict__ nfeat) {
    const int NH = N_NODES * 96;
    const int NH2 = N_NODES * 128;
    int total = NH + NH + NH2 + N_NODES;
    for (int i = blockIdx.x * blockDim.x + threadIdx.x; i < total;
         i += gridDim.x * blockDim.x) {
        if (i < NH) {
            int node = i / 96, j = i % 96;
            ((float*)g_h)[i] = (j < 48) ? nfeat[node * 48 + j] : 0.0f;
        } else if (i < 2 * NH) {
            ((float*)g_hn1)[i - NH] = 0.0f;
        } else if (i < 2 * NH + NH2) {
            ((float*)g_hn2)[i - 2 * NH] = 0.0f;
        } else {
            g_deg[i - 2 * NH - NH2] = 0.0f;
        }
    }
}

// ---------------- edge stage 1: e=relu(efeat@We+be); m=nfeat[src]*e; ----------------
// scatter-add m into h[dst, 48:96]; count degree. Warp per edge, 16 edges/warp.
#define EK1_EPW 16
__global__ __launch_bounds__(256) void k_edge1(
    const float* __restrict__ efeat, const int* __restrict__ src,
    const int* __restrict__ dst, const float* __restrict__ nfeat,
    const float* __restrict__ We, const float* __restrict__ be) {
    const int lane = threadIdx.x & 31;
    const int wl = threadIdx.x >> 5;
    const int gwarp = (blockIdx.x * blockDim.x + threadIdx.x) >> 5;

    // We columns in registers: lane owns output cols {lane, 32+lane(if lane<16)}
    float w0[32], w1[32];
#pragma unroll
    for (int k = 0; k < 32; k++) w0[k] = We[k * 48 + lane];
#pragma unroll
    for (int k = 0; k < 32; k++) w1[k] = (lane < 16) ? We[k * 48 + 32 + lane] : 0.0f;
    const float bia0 = be[lane];
    const float bia1 = (lane < 16) ? be[32 + lane] : 0.0f;

    __shared__ __align__(16) float se[8][48];

    int e0 = gwarp * EK1_EPW;
    for (int it = 0; it < EK1_EPW; it++) {
        int e = e0 + it;
        if (e >= N_EDGES) break;
        float ef = efeat[e * 32 + lane];
        float a0 = bia0, a1 = bia1;
#pragma unroll
        for (int k = 0; k < 32; k++) {
            float v = __shfl_sync(0xffffffffu, ef, k);
            a0 = fmaf(v, w0[k], a0);
            a1 = fmaf(v, w1[k], a1);
        }
        a0 = fmaxf(a0, 0.0f);
        a1 = fmaxf(a1, 0.0f);
        se[wl][lane] = a0;
        if (lane < 16) se[wl][32 + lane] = a1;
        __syncwarp();
        int s = src[e], d = dst[e];
        if (lane < 12) {
            float4 ev = ((float4*)se[wl])[lane];
            float4 nf = ((const float4*)nfeat)[s * 12 + lane];
            float4 m = make_float4(ev.x * nf.x, ev.y * nf.y, ev.z * nf.z, ev.w * nf.w);
            red_add4((float*)&g_h[d * 24 + 12 + lane], m);
        } else if (lane == 12) {
            red_add1(&g_deg[d], 1.0f);
        }
        __syncwarp();
    }
}

// ---------------- finalize: h_neigh0 /= deg ; compute g_inv ----------------
__global__ void k_fin() {
    const int NS = N_NODES * 48;
    int total = NS + N_NODES;
    for (int i = blockIdx.x * blockDim.x + threadIdx.x; i < total;
         i += gridDim.x * blockDim.x) {
        if (i < NS) {
            int node = i / 48, j = i % 48;
            float iv = __fdividef(1.0f, fmaxf(g_deg[node], 1.0f));
            ((float*)g_h)[node * 96 + 48 + j] *= iv;
        } else {
            int node = i - NS;
            g_inv[node] = __fdividef(1.0f, fmaxf(g_deg[node], 1.0f));
        }
    }
}

// ---------------- edge stage 2: hn1[dst] += h[src] (96 floats = 24 float4) ----------------
__global__ __launch_bounds__(192) void k_edge2(const int* __restrict__ src,
                                               const int* __restrict__ dst) {
    int e = blockIdx.x * 8 + threadIdx.x / 24;
    int c = threadIdx.x % 24;
    if (e >= N_EDGES) return;
    int s = src[e], d = dst[e];
    float4 v = g_h[s * 24 + c];
    red_add4((float*)&g_hn1[d * 24 + c], v);
}

// ---------------- GEMM1: h1 = relu(h@W1s + (hn1*inv)@W1n + b1) ----------------
// block: 128 thr = 4 warps, 8 nodes/warp, lane = 4-col group (128 cols).
__global__ __launch_bounds__(128) void k_gemm1(const float* __restrict__ W1s,
                                               const float* __restrict__ W1n,
                                               const float* __restrict__ b1) {
    __shared__ __align__(16) float As[32][192];  // [node][k], k<96:h, k>=96:hn1*inv
    const int tid = threadIdx.x;
    const int node0 = blockIdx.x * 32;
    for (int i = tid; i < 32 * 48; i += 128) {
        int n = i / 48, kq = i % 48;
        int node = node0 + n;
        float4 v;
        if (kq < 24) {
            v = g_h[node * 24 + kq];
        } else {
            v = g_hn1[node * 24 + (kq - 24)];
            float iv = g_inv[node];
            v.x *= iv; v.y *= iv; v.z *= iv; v.w *= iv;
        }
        ((float4*)As[n])[kq] = v;
    }
    __syncthreads();

    const int lane = tid & 31;
    const int nb = (tid >> 5) * 8;
    const float4* W1s4 = (const float4*)W1s;
    const float4* W1n4 = (const float4*)W1n;
    float4 bb = ((const float4*)b1)[lane];
    float4 acc[8];
#pragma unroll
    for (int n = 0; n < 8; n++) acc[n] = bb;

#pragma unroll 4
    for (int k = 0; k < 96; k++) {
        float4 wv = W1s4[k * 32 + lane];
#pragma unroll
        for (int n = 0; n < 8; n++) {
            float a = As[nb + n][k];
            acc[n].x = fmaf(a, wv.x, acc[n].x);
            acc[n].y = fmaf(a, wv.y, acc[n].y);
            acc[n].z = fmaf(a, wv.z, acc[n].z);
            acc[n].w = fmaf(a, wv.w, acc[n].w);
        }
    }
#pragma unroll 4
    for (int k = 0; k < 96; k++) {
        float4 wv = W1n4[k * 32 + lane];
#pragma unroll
        for (int n = 0; n < 8; n++) {
            float a = As[nb + n][96 + k];
            acc[n].x = fmaf(a, wv.x, acc[n].x);
            acc[n].y = fmaf(a, wv.y, acc[n].y);
            acc[n].z = fmaf(a, wv.z, acc[n].z);
            acc[n].w = fmaf(a, wv.w, acc[n].w);
        }
    }
#pragma unroll
    for (int n = 0; n < 8; n++) {
        float4 r = acc[n];
        r.x = fmaxf(r.x, 0.0f); r.y = fmaxf(r.y, 0.0f);
        r.z = fmaxf(r.z, 0.0f); r.w = fmaxf(r.w, 0.0f);
        g_h1[(node0 + nb + n) * 32 + lane] = r;
    }
}

// ---------------- edge stage 3: hn2[dst] += h1[src] (128 floats, warp/edge) ----------------
__global__ __launch_bounds__(256) void k_edge3(const int* __restrict__ src,
                                               const int* __restrict__ dst) {
    int e = blockIdx.x * 8 + (threadIdx.x >> 5);
    int lane = threadIdx.x & 31;
    if (e >= N_EDGES) return;
    int s = src[e], d = dst[e];
    float4 v = g_h1[s * 32 + lane];
    red_add4((float*)&g_hn2[d * 32 + lane], v);
}

// ---------------- GEMM2: out = h1@W2s + (hn2*inv)@W2n + b2 ----------------
// block: 64 thr = 2 warps; each warp: half-warps = two 8-node groups, cg = lane&15 (64 cols).
__global__ __launch_bounds__(64) void k_gemm2(const float* __restrict__ W2s,
                                              const float* __restrict__ W2n,
                                              const float* __restrict__ b2,
                                              float* __restrict__ out) {
    __shared__ __align__(16) float As[32][256];
    const int tid = threadIdx.x;
    const int node0 = blockIdx.x * 32;
    for (int i = tid; i < 32 * 64; i += 64) {
        int n = i / 64, kq = i % 64;
        int node = node0 + n;
        float4 v;
        if (kq < 32) {
            v = g_h1[node * 32 + kq];
        } else {
            v = g_hn2[node * 32 + (kq - 32)];
            float iv = g_inv[node];
            v.x *= iv; v.y *= iv; v.z *= iv; v.w *= iv;
        }
        ((float4*)As[n])[kq] = v;
    }
    __syncthreads();

    const int lane = tid & 31;
    const int cg = lane & 15;
    const int nb = (tid >> 5) * 16 + (lane >> 4) * 8;
    const float4* W2s4 = (const float4*)W2s;
    const float4* W2n4 = (const float4*)W2n;
    float4 bb = ((const float4*)b2)[cg];
    float4 acc[8];
#pragma unroll
    for (int n = 0; n < 8; n++) acc[n] = bb;

#pragma unroll 4
    for (int k = 0; k < 128; k++) {
        float4 wv = W2s4[k * 16 + cg];
#pragma unroll
        for (int n = 0; n < 8; n++) {
            float a = As[nb + n][k];
            acc[n].x = fmaf(a, wv.x, acc[n].x);
            acc[n].y = fmaf(a, wv.y, acc[n].y);
            acc[n].z = fmaf(a, wv.z, acc[n].z);
            acc[n].w = fmaf(a, wv.w, acc[n].w);
        }
    }
#pragma unroll 4
    for (int k = 0; k < 128; k++) {
        float4 wv = W2n4[k * 16 + cg];
#pragma unroll
        for (int n = 0; n < 8; n++) {
            float a = As[nb + n][128 + k];
            acc[n].x = fmaf(a, wv.x, acc[n].x);
            acc[n].y = fmaf(a, wv.y, acc[n].y);
            acc[n].z = fmaf(a, wv.z, acc[n].z);
            acc[n].w = fmaf(a, wv.w, acc[n].w);
        }
    }
    float4* out4 = (float4*)out;
#pragma unroll
    for (int n = 0; n < 8; n++) {
        out4[(node0 + nb + n) * 16 + cg] = acc[n];
    }
}

// ---------------- launch ----------------
extern "C" void kernel_launch(void* const* d_in, const int* in_sizes, int n_in,
                              void* d_out, int out_size) {
    const float* nfeat = (const float*)d_in[0];
    const float* efeat = (const float*)d_in[1];
    const int*   src   = (const int*)d_in[2];
    const int*   dst   = (const int*)d_in[3];
    const float* We    = (const float*)d_in[4];
    const float* be    = (const float*)d_in[5];
    const float* W1s   = (const float*)d_in[6];
    const float* W1n   = (const float*)d_in[7];
    const float* b1    = (const float*)d_in[8];
    const float* W2s   = (const float*)d_in[9];
    const float* W2n   = (const float*)d_in[10];
    const float* b2    = (const float*)d_in[11];
    float* out = (float*)d_out;

    const int init_total = N_NODES * 96 * 2 + N_NODES * 128 + N_NODES;
    k_init<<<(init_total + 255) / 256, 256>>>(nfeat);

    const int ek1_warps = (N_EDGES + EK1_EPW - 1) / EK1_EPW;  // 100000
    k_edge1<<<(ek1_warps + 7) / 8, 256>>>(efeat, src, dst, nfeat, We, be);

    const int fin_total = N_NODES * 48 + N_NODES;
    k_fin<<<(fin_total + 255) / 256, 256>>>();

    k_edge2<<<(N_EDGES + 7) / 8, 192>>>(src, dst);

    k_gemm1<<<N_NODES / 32, 128>>>(W1s, W1n, b1);

    k_edge3<<<(N_EDGES + 7) / 8, 256>>>(src, dst);

    k_gemm2<<<N_NODES / 32, 64>>>(W2s, W2n, b2, out);
}

// round 2
// speedup vs baseline: 1.1481x; 1.1481x over previous
#include <cuda_runtime.h>
#include <cstdint>

#define N_NODES 100000
#define N_EDGES 1600000
#define IN_F   48
#define EDGE_F 32
#define HID_F  128
#define OUT_F  64

typedef unsigned long long ull;

// ---------------- scratch (device globals; allocation-free) ----------------
__device__ float4 g_h[N_NODES * 24];     // [N,96]  = [nfeat | h_neigh0]
__device__ float4 g_hn1[N_NODES * 24];   // [N,96]  accum of h[src] per dst
__device__ float4 g_h1[N_NODES * 32];    // [N,128]
__device__ float4 g_y[N_NODES * 16];     // [N,64]  = h1 @ W2n
__device__ float4 g_hn2y[N_NODES * 16];  // [N,64]  accum of y[src] per dst
__device__ float  g_deg[N_NODES];
__device__ float  g_inv[N_NODES];

// packed weights: element = (W[2kp][c], W[2kp+1][c]) as f32x2 in a u64
__device__ ull g_Wep[16 * 48];           // We: 32k x 48c -> 16kp x 48
__device__ ull g_W1p[96 * 128];          // [W1s;W1n]: 192k x 128 -> 96kp x 128
__device__ ull g_W2sp[64 * 64];          // W2s: 128k x 64 -> 64kp x 64
__device__ ull g_W2np[64 * 64];          // W2n

// ---------------- helpers ----------------
__device__ __forceinline__ ull ffma2(ull a, ull b, ull c) {
    ull d;
    asm("fma.rn.f32x2 %0, %1, %2, %3;" : "=l"(d) : "l"(a), "l"(b), "l"(c));
    return d;
}
__device__ __forceinline__ ull f2u(float x, float y) {
    ull r;
    asm("mov.b64 %0, {%1,%2};" : "=l"(r) : "f"(x), "f"(y));
    return r;
}
__device__ __forceinline__ float2 u2f(ull v) {
    float2 r;
    asm("mov.b64 {%0,%1}, %2;" : "=f"(r.x), "=f"(r.y) : "l"(v));
    return r;
}
__device__ __forceinline__ void red_add4(float* p, float4 v) {
    asm volatile("red.global.add.v4.f32 [%0], {%1,%2,%3,%4};"
                 :: "l"(p), "f"(v.x), "f"(v.y), "f"(v.z), "f"(v.w) : "memory");
}
__device__ __forceinline__ void red_add1(float* p, float v) {
    asm volatile("red.global.add.f32 [%0], %1;" :: "l"(p), "f"(v) : "memory");
}

// ---------------- weight prepack ----------------
__global__ void k_prep(const float* __restrict__ We, const float* __restrict__ W1s,
                       const float* __restrict__ W1n, const float* __restrict__ W2s,
                       const float* __restrict__ W2n) {
    const int T0 = 16 * 48;            // Wep
    const int T1 = T0 + 96 * 128;      // W1p
    const int T2 = T1 + 64 * 64;       // W2sp
    const int T3 = T2 + 64 * 64;       // W2np
    for (int i = blockIdx.x * blockDim.x + threadIdx.x; i < T3;
         i += gridDim.x * blockDim.x) {
        if (i < T0) {
            int kp = i / 48, c = i % 48;
            g_Wep[i] = f2u(We[(2 * kp) * 48 + c], We[(2 * kp + 1) * 48 + c]);
        } else if (i < T1) {
            int j = i - T0, kp = j / 128, c = j % 128;
            const float* W = (kp < 48) ? W1s : W1n;
            int k0 = (kp < 48) ? 2 * kp : 2 * (kp - 48);
            g_W1p[j] = f2u(W[k0 * 128 + c], W[(k0 + 1) * 128 + c]);
        } else if (i < T2) {
            int j = i - T1, kp = j / 64, c = j % 64;
            g_W2sp[j] = f2u(W2s[(2 * kp) * 64 + c], W2s[(2 * kp + 1) * 64 + c]);
        } else {
            int j = i - T2, kp = j / 64, c = j % 64;
            g_W2np[j] = f2u(W2n[(2 * kp) * 64 + c], W2n[(2 * kp + 1) * 64 + c]);
        }
    }
}

// ---------------- init: build h left half, zero accumulators ----------------
__global__ void k_init(const float* __restrict__ nfeat) {
    const int NH = N_NODES * 96;
    const int NY = N_NODES * 64;
    int total = NH + NH + NY + N_NODES;
    for (int i = blockIdx.x * blockDim.x + threadIdx.x; i < total;
         i += gridDim.x * blockDim.x) {
        if (i < NH) {
            int node = i / 96, j = i % 96;
            ((float*)g_h)[i] = (j < 48) ? nfeat[node * 48 + j] : 0.0f;
        } else if (i < 2 * NH) {
            ((float*)g_hn1)[i - NH] = 0.0f;
        } else if (i < 2 * NH + NY) {
            ((float*)g_hn2y)[i - 2 * NH] = 0.0f;
        } else {
            g_deg[i - 2 * NH - NY] = 0.0f;
        }
    }
}

// ---------------- edge stage 1: e=relu(efeat@We+be); m=nfeat[src]*e ----------------
#define EK1_EPW 16
__global__ __launch_bounds__(256) void k_edge1(
    const float* __restrict__ efeat, const int* __restrict__ src,
    const int* __restrict__ dst, const float* __restrict__ nfeat,
    const float* __restrict__ be) {
    const int lane = threadIdx.x & 31;
    const int wl = threadIdx.x >> 5;
    const int gwarp = (blockIdx.x * blockDim.x + threadIdx.x) >> 5;

    ull wp0[16], wp1[16];
#pragma unroll
    for (int kp = 0; kp < 16; kp++) wp0[kp] = g_Wep[kp * 48 + lane];
#pragma unroll
    for (int kp = 0; kp < 16; kp++)
        wp1[kp] = (lane < 16) ? g_Wep[kp * 48 + 32 + lane] : 0ull;
    const float bia0 = be[lane];
    const float bia1 = (lane < 16) ? be[32 + lane] : 0.0f;

    __shared__ __align__(16) float se[8][48];

    int e0 = gwarp * EK1_EPW;
    for (int it = 0; it < EK1_EPW; it++) {
        int e = e0 + it;
        if (e >= N_EDGES) break;
        int s = src[e], d = dst[e];
        float ef = efeat[e * 32 + lane];
        se[wl][lane] = ef;
        __syncwarp();
        ull a0 = 0ull, a1 = 0ull;
#pragma unroll
        for (int kp = 0; kp < 16; kp++) {
            ull a2 = *(const ull*)&se[wl][2 * kp];
            a0 = ffma2(a2, wp0[kp], a0);
            a1 = ffma2(a2, wp1[kp], a1);
        }
        __syncwarp();
        float2 p0 = u2f(a0);
        float r0 = fmaxf(p0.x + p0.y + bia0, 0.0f);
        float2 p1 = u2f(a1);
        float r1 = fmaxf(p1.x + p1.y + bia1, 0.0f);
        se[wl][lane] = r0;
        if (lane < 16) se[wl][32 + lane] = r1;
        __syncwarp();
        if (lane < 12) {
            float4 ev = ((float4*)se[wl])[lane];
            float4 nf = ((const float4*)nfeat)[s * 12 + lane];
            float4 m = make_float4(ev.x * nf.x, ev.y * nf.y, ev.z * nf.z, ev.w * nf.w);
            red_add4((float*)&g_h[d * 24 + 12 + lane], m);
        } else if (lane == 12) {
            red_add1(&g_deg[d], 1.0f);
        }
        __syncwarp();
    }
}

// ---------------- finalize: h_neigh0 /= deg ; compute g_inv ----------------
__global__ void k_fin() {
    const int NS = N_NODES * 48;
    int total = NS + N_NODES;
    for (int i = blockIdx.x * blockDim.x + threadIdx.x; i < total;
         i += gridDim.x * blockDim.x) {
        if (i < NS) {
            int node = i / 48, j = i % 48;
            float iv = __fdividef(1.0f, fmaxf(g_deg[node], 1.0f));
            ((float*)g_h)[node * 96 + 48 + j] *= iv;
        } else {
            int node = i - NS;
            g_inv[node] = __fdividef(1.0f, fmaxf(g_deg[node], 1.0f));
        }
    }
}

// ---------------- edge stage 2: hn1[dst] += h[src], 4 edges/thread batched ----------------
__global__ __launch_bounds__(192) void k_edge2(const int* __restrict__ src,
                                               const int* __restrict__ dst) {
    const int tid = threadIdx.x;
    const int c = tid % 24;
    const int es = tid / 24;  // 0..7
    const int ebase = blockIdx.x * 32 + es;
    int s[4], d[4];
#pragma unroll
    for (int j = 0; j < 4; j++) {
        int e = ebase + j * 8;
        s[j] = src[e];
        d[j] = dst[e];
    }
    float4 v[4];
#pragma unroll
    for (int j = 0; j < 4; j++) v[j] = g_h[s[j] * 24 + c];
#pragma unroll
    for (int j = 0; j < 4; j++) red_add4((float*)&g_hn1[d[j] * 24 + c], v[j]);
}

// ---------------- GEMM1: h1 = relu(h@W1s + (hn1*inv)@W1n + b1), packed f32x2 ----------------
__global__ __launch_bounds__(128) void k_gemm1(const float* __restrict__ b1) {
    __shared__ __align__(16) float As[32][192];
    const int tid = threadIdx.x;
    const int node0 = blockIdx.x * 32;
    for (int i = tid; i < 32 * 48; i += 128) {
        int n = i / 48, kq = i % 48;
        int node = node0 + n;
        float4 v;
        if (kq < 24) {
            v = g_h[node * 24 + kq];
        } else {
            v = g_hn1[node * 24 + (kq - 24)];
            float iv = g_inv[node];
            v.x *= iv; v.y *= iv; v.z *= iv; v.w *= iv;
        }
        ((float4*)As[n])[kq] = v;
    }
    __syncthreads();

    const int lane = tid & 31;
    const int nb = (tid >> 5) * 8;
    const int c0 = lane * 4;
    ull acc[8][4];
#pragma unroll
    for (int n = 0; n < 8; n++)
#pragma unroll
        for (int j = 0; j < 4; j++) acc[n][j] = 0ull;

    for (int kq = 0; kq < 48; kq++) {
        const int kpA = 2 * kq, kpB = 2 * kq + 1;
        ulonglong2 wA0 = *(const ulonglong2*)&g_W1p[kpA * 128 + c0];
        ulonglong2 wA1 = *(const ulonglong2*)&g_W1p[kpA * 128 + c0 + 2];
        ulonglong2 wB0 = *(const ulonglong2*)&g_W1p[kpB * 128 + c0];
        ulonglong2 wB1 = *(const ulonglong2*)&g_W1p[kpB * 128 + c0 + 2];
#pragma unroll
        for (int n = 0; n < 8; n++) {
            ulonglong2 a = *(const ulonglong2*)&As[nb + n][4 * kq];
            acc[n][0] = ffma2(a.x, wA0.x, acc[n][0]);
            acc[n][1] = ffma2(a.x, wA0.y, acc[n][1]);
            acc[n][2] = ffma2(a.x, wA1.x, acc[n][2]);
            acc[n][3] = ffma2(a.x, wA1.y, acc[n][3]);
            acc[n][0] = ffma2(a.y, wB0.x, acc[n][0]);
            acc[n][1] = ffma2(a.y, wB0.y, acc[n][1]);
            acc[n][2] = ffma2(a.y, wB1.x, acc[n][2]);
            acc[n][3] = ffma2(a.y, wB1.y, acc[n][3]);
        }
    }

    float4 bb = *(const float4*)&b1[c0];
#pragma unroll
    for (int n = 0; n < 8; n++) {
        float2 p0 = u2f(acc[n][0]), p1 = u2f(acc[n][1]);
        float2 p2 = u2f(acc[n][2]), p3 = u2f(acc[n][3]);
        float4 r;
        r.x = fmaxf(p0.x + p0.y + bb.x, 0.0f);
        r.y = fmaxf(p1.x + p1.y + bb.y, 0.0f);
        r.z = fmaxf(p2.x + p2.y + bb.z, 0.0f);
        r.w = fmaxf(p3.x + p3.y + bb.w, 0.0f);
        g_h1[(node0 + nb + n) * 32 + lane] = r;
    }
}

// ---------------- GEMM-Y: y = h1 @ W2n (projection push-down), packed ----------------
__global__ __launch_bounds__(64) void k_gemmy() {
    __shared__ __align__(16) float As[32][128];
    const int tid = threadIdx.x;
    const int node0 = blockIdx.x * 32;
    for (int i = tid; i < 32 * 32; i += 64) {
        int n = i / 32, kq = i % 32;
        ((float4*)As[n])[kq] = g_h1[(node0 + n) * 32 + kq];
    }
    __syncthreads();

    const int lane = tid & 31;
    const int cg = lane & 15;
    const int c0 = cg * 4;
    const int nb = (tid >> 5) * 16 + (lane >> 4) * 8;
    ull acc[8][4];
#pragma unroll
    for (int n = 0; n < 8; n++)
#pragma unroll
        for (int j = 0; j < 4; j++) acc[n][j] = 0ull;

    for (int kq = 0; kq < 32; kq++) {
        const int kpA = 2 * kq, kpB = 2 * kq + 1;
        ulonglong2 wA0 = *(const ulonglong2*)&g_W2np[kpA * 64 + c0];
        ulonglong2 wA1 = *(const ulonglong2*)&g_W2np[kpA * 64 + c0 + 2];
        ulonglong2 wB0 = *(const ulonglong2*)&g_W2np[kpB * 64 + c0];
        ulonglong2 wB1 = *(const ulonglong2*)&g_W2np[kpB * 64 + c0 + 2];
#pragma unroll
        for (int n = 0; n < 8; n++) {
            ulonglong2 a = *(const ulonglong2*)&As[nb + n][4 * kq];
            acc[n][0] = ffma2(a.x, wA0.x, acc[n][0]);
            acc[n][1] = ffma2(a.x, wA0.y, acc[n][1]);
            acc[n][2] = ffma2(a.x, wA1.x, acc[n][2]);
            acc[n][3] = ffma2(a.x, wA1.y, acc[n][3]);
            acc[n][0] = ffma2(a.y, wB0.x, acc[n][0]);
            acc[n][1] = ffma2(a.y, wB0.y, acc[n][1]);
            acc[n][2] = ffma2(a.y, wB1.x, acc[n][2]);
            acc[n][3] = ffma2(a.y, wB1.y, acc[n][3]);
        }
    }
#pragma unroll
    for (int n = 0; n < 8; n++) {
        float2 p0 = u2f(acc[n][0]), p1 = u2f(acc[n][1]);
        float2 p2 = u2f(acc[n][2]), p3 = u2f(acc[n][3]);
        float4 r;
        r.x = p0.x + p0.y;
        r.y = p1.x + p1.y;
        r.z = p2.x + p2.y;
        r.w = p3.x + p3.y;
        g_y[(node0 + nb + n) * 16 + cg] = r;
    }
}

// ---------------- edge stage 3: hn2y[dst] += y[src] (64 floats), batched ----------------
__global__ __launch_bounds__(256) void k_edge3(const int* __restrict__ src,
                                               const int* __restrict__ dst) {
    const int tid = threadIdx.x;
    const int c = tid & 15;
    const int es = tid >> 4;  // 0..15
    const int ebase = blockIdx.x * 64 + es;
    int s[4], d[4];
#pragma unroll
    for (int j = 0; j < 4; j++) {
        int e = ebase + j * 16;
        s[j] = src[e];
        d[j] = dst[e];
    }
    float4 v[4];
#pragma unroll
    for (int j = 0; j < 4; j++) v[j] = g_y[s[j] * 16 + c];
#pragma unroll
    for (int j = 0; j < 4; j++) red_add4((float*)&g_hn2y[d[j] * 16 + c], v[j]);
}

// ---------------- GEMM2s: out = h1@W2s + b2 + hn2y*inv ----------------
__global__ __launch_bounds__(64) void k_gemm2s(const float* __restrict__ b2,
                                               float* __restrict__ out) {
    __shared__ __align__(16) float As[32][128];
    const int tid = threadIdx.x;
    const int node0 = blockIdx.x * 32;
    for (int i = tid; i < 32 * 32; i += 64) {
        int n = i / 32, kq = i % 32;
        ((float4*)As[n])[kq] = g_h1[(node0 + n) * 32 + kq];
    }
    __syncthreads();

    const int lane = tid & 31;
    const int cg = lane & 15;
    const int c0 = cg * 4;
    const int nb = (tid >> 5) * 16 + (lane >> 4) * 8;
    ull acc[8][4];
#pragma unroll
    for (int n = 0; n < 8; n++)
#pragma unroll
        for (int j = 0; j < 4; j++) acc[n][j] = 0ull;

    for (int kq = 0; kq < 32; kq++) {
        const int kpA = 2 * kq, kpB = 2 * kq + 1;
        ulonglong2 wA0 = *(const ulonglong2*)&g_W2sp[kpA * 64 + c0];
        ulonglong2 wA1 = *(const ulonglong2*)&g_W2sp[kpA * 64 + c0 + 2];
        ulonglong2 wB0 = *(const ulonglong2*)&g_W2sp[kpB * 64 + c0];
        ulonglong2 wB1 = *(const ulonglong2*)&g_W2sp[kpB * 64 + c0 + 2];
#pragma unroll
        for (int n = 0; n < 8; n++) {
            ulonglong2 a = *(const ulonglong2*)&As[nb + n][4 * kq];
            acc[n][0] = ffma2(a.x, wA0.x, acc[n][0]);
            acc[n][1] = ffma2(a.x, wA0.y, acc[n][1]);
            acc[n][2] = ffma2(a.x, wA1.x, acc[n][2]);
            acc[n][3] = ffma2(a.x, wA1.y, acc[n][3]);
            acc[n][0] = ffma2(a.y, wB0.x, acc[n][0]);
            acc[n][1] = ffma2(a.y, wB0.y, acc[n][1]);
            acc[n][2] = ffma2(a.y, wB1.x, acc[n][2]);
            acc[n][3] = ffma2(a.y, wB1.y, acc[n][3]);
        }
    }

    float4 bb = *(const float4*)&b2[c0];
    float4* out4 = (float4*)out;
#pragma unroll
    for (int n = 0; n < 8; n++) {
        int node = node0 + nb + n;
        float iv = g_inv[node];
        float4 hz = g_hn2y[node * 16 + cg];
        float2 p0 = u2f(acc[n][0]), p1 = u2f(acc[n][1]);
        float2 p2 = u2f(acc[n][2]), p3 = u2f(acc[n][3]);
        float4 r;
        r.x = p0.x + p0.y + bb.x + hz.x * iv;
        r.y = p1.x + p1.y + bb.y + hz.y * iv;
        r.z = p2.x + p2.y + bb.z + hz.z * iv;
        r.w = p3.x + p3.y + bb.w + hz.w * iv;
        out4[node * 16 + cg] = r;
    }
}

// ---------------- launch ----------------
extern "C" void kernel_launch(void* const* d_in, const int* in_sizes, int n_in,
                              void* d_out, int out_size) {
    const float* nfeat = (const float*)d_in[0];
    const float* efeat = (const float*)d_in[1];
    const int*   src   = (const int*)d_in[2];
    const int*   dst   = (const int*)d_in[3];
    const float* We    = (const float*)d_in[4];
    const float* be    = (const float*)d_in[5];
    const float* W1s   = (const float*)d_in[6];
    const float* W1n   = (const float*)d_in[7];
    const float* b1    = (const float*)d_in[8];
    const float* W2s   = (const float*)d_in[9];
    const float* W2n   = (const float*)d_in[10];
    const float* b2    = (const float*)d_in[11];
    float* out = (float*)d_out;

    k_prep<<<84, 256>>>(We, W1s, W1n, W2s, W2n);

    const int init_total = N_NODES * 96 * 2 + N_NODES * 64 + N_NODES;
    k_init<<<(init_total + 255) / 256, 256>>>(nfeat);

    const int ek1_warps = (N_EDGES + EK1_EPW - 1) / EK1_EPW;  // 100000
    k_edge1<<<(ek1_warps + 7) / 8, 256>>>(efeat, src, dst, nfeat, be);

    const int fin_total = N_NODES * 48 + N_NODES;
    k_fin<<<(fin_total + 255) / 256, 256>>>();

    k_edge2<<<N_EDGES / 32, 192>>>(src, dst);

    k_gemm1<<<N_NODES / 32, 128>>>(b1);

    k_gemmy<<<N_NODES / 32, 64>>>();

    k_edge3<<<N_EDGES / 64, 256>>>(src, dst);

    k_gemm2s<<<N_NODES / 32, 64>>>(b2, out);
}

// round 3
// speedup vs baseline: 1.3272x; 1.1560x over previous
#include <cuda_runtime.h>
#include <cstdint>

#define N_NODES 100000
#define N_EDGES 1600000
#define IN_F   48
#define EDGE_F 32
#define HID_F  128
#define OUT_F  64

typedef unsigned long long ull;

#define NB_SCAN 391   // ceil(N_NODES/256)

// ---------------- scratch (device globals; allocation-free) ----------------
__device__ float4 g_h[N_NODES * 24];     // [N,96]  = [nfeat | mean-neigh0]
__device__ float4 g_hn1[N_NODES * 24];   // [N,96]  mean of h[src] per dst
__device__ float4 g_h1[N_NODES * 32];    // [N,128]
__device__ float4 g_y[N_NODES * 16];     // [N,64]  = h1 @ W2n
__device__ float4 g_hn2y[N_NODES * 16];  // [N,64]  mean of y[src] per dst
__device__ unsigned g_cnt[N_NODES];      // in-degree
__device__ unsigned g_off[N_NODES];      // CSR offsets (exclusive scan of cnt)
__device__ unsigned g_cur[N_NODES];      // scatter cursors
__device__ unsigned g_bsum[512];         // scan block sums
__device__ int g_pe[N_EDGES];            // edge ids grouped by dst
__device__ int g_ps[N_EDGES];            // src ids grouped by dst

// packed weights: element = (W[2kp][c], W[2kp+1][c]) as f32x2 in a u64
__device__ ull g_Wep[16 * 48];           // We: 32k x 48c
__device__ ull g_W1p[96 * 128];          // [W1s;W1n]: 192k x 128
__device__ ull g_W2sp[64 * 64];          // W2s
__device__ ull g_W2np[64 * 64];          // W2n

// ---------------- helpers ----------------
__device__ __forceinline__ ull ffma2(ull a, ull b, ull c) {
    ull d;
    asm("fma.rn.f32x2 %0, %1, %2, %3;" : "=l"(d) : "l"(a), "l"(b), "l"(c));
    return d;
}
__device__ __forceinline__ ull f2u(float x, float y) {
    ull r;
    asm("mov.b64 %0, {%1,%2};" : "=l"(r) : "f"(x), "f"(y));
    return r;
}
__device__ __forceinline__ float2 u2f(ull v) {
    float2 r;
    asm("mov.b64 {%0,%1}, %2;" : "=f"(r.x), "=f"(r.y) : "l"(v));
    return r;
}
__device__ __forceinline__ void red_u32(unsigned* p, unsigned v) {
    asm volatile("red.global.add.u32 [%0], %1;" :: "l"(p), "r"(v) : "memory");
}

// ---------------- weight prepack + cnt zero ----------------
__global__ void k_prep(const float* __restrict__ We, const float* __restrict__ W1s,
                       const float* __restrict__ W1n, const float* __restrict__ W2s,
                       const float* __restrict__ W2n) {
    const int T0 = 16 * 48;
    const int T1 = T0 + 96 * 128;
    const int T2 = T1 + 64 * 64;
    const int T3 = T2 + 64 * 64;
    const int T4 = T3 + N_NODES;
    for (int i = blockIdx.x * blockDim.x + threadIdx.x; i < T4;
         i += gridDim.x * blockDim.x) {
        if (i < T0) {
            int kp = i / 48, c = i % 48;
            g_Wep[i] = f2u(We[(2 * kp) * 48 + c], We[(2 * kp + 1) * 48 + c]);
        } else if (i < T1) {
            int j = i - T0, kp = j / 128, c = j % 128;
            const float* W = (kp < 48) ? W1s : W1n;
            int k0 = (kp < 48) ? 2 * kp : 2 * (kp - 48);
            g_W1p[j] = f2u(W[k0 * 128 + c], W[(k0 + 1) * 128 + c]);
        } else if (i < T2) {
            int j = i - T1, kp = j / 64, c = j % 64;
            g_W2sp[j] = f2u(W2s[(2 * kp) * 64 + c], W2s[(2 * kp + 1) * 64 + c]);
        } else if (i < T3) {
            int j = i - T2, kp = j / 64, c = j % 64;
            g_W2np[j] = f2u(W2n[(2 * kp) * 64 + c], W2n[(2 * kp + 1) * 64 + c]);
        } else {
            g_cnt[i - T3] = 0u;
        }
    }
}

// ---------------- CSR build ----------------
__global__ void k_hist(const int* __restrict__ dst) {
    for (int e = blockIdx.x * blockDim.x + threadIdx.x; e < N_EDGES;
         e += gridDim.x * blockDim.x)
        red_u32(&g_cnt[dst[e]], 1u);
}

__global__ void k_scan1() {
    __shared__ unsigned sh[256];
    int i = blockIdx.x * 256 + threadIdx.x;
    unsigned v = (i < N_NODES) ? g_cnt[i] : 0u;
    sh[threadIdx.x] = v;
    __syncthreads();
#pragma unroll
    for (int ofs = 1; ofs < 256; ofs <<= 1) {
        unsigned t = (threadIdx.x >= ofs) ? sh[threadIdx.x - ofs] : 0u;
        __syncthreads();
        sh[threadIdx.x] += t;
        __syncthreads();
    }
    if (i < N_NODES) g_off[i] = sh[threadIdx.x] - v;  // local exclusive
    if (threadIdx.x == 255) g_bsum[blockIdx.x] = sh[255];
}

__global__ void k_scan2() {
    __shared__ unsigned sh[512];
    int t = threadIdx.x;
    unsigned v = (t < NB_SCAN) ? g_bsum[t] : 0u;
    sh[t] = v;
    __syncthreads();
#pragma unroll
    for (int ofs = 1; ofs < 512; ofs <<= 1) {
        unsigned x = (t >= ofs) ? sh[t - ofs] : 0u;
        __syncthreads();
        sh[t] += x;
        __syncthreads();
    }
    g_bsum[t] = sh[t] - v;  // exclusive base per block
}

__global__ void k_scan3() {
    int i = blockIdx.x * 256 + threadIdx.x;
    if (i < N_NODES) {
        unsigned o = g_off[i] + g_bsum[blockIdx.x];
        g_off[i] = o;
        g_cur[i] = o;
    }
}

__global__ void k_scatter(const int* __restrict__ src, const int* __restrict__ dst) {
    for (int e = blockIdx.x * blockDim.x + threadIdx.x; e < N_EDGES;
         e += gridDim.x * blockDim.x) {
        int d = dst[e];
        unsigned pos = atomicAdd(&g_cur[d], 1u);
        g_pe[pos] = e;
        g_ps[pos] = src[e];
    }
}

// ---------------- stage A: per-dst edge-MLP reduction ----------------
// h[d] = [nfeat[d] | mean_e relu(efeat[e]@We+be) * nfeat[src[e]] ]
__global__ __launch_bounds__(256) void k_dstA(
    const float* __restrict__ efeat, const float* __restrict__ nfeat,
    const float* __restrict__ be) {
    const int lane = threadIdx.x & 31;
    const int wl = threadIdx.x >> 5;
    const int d = blockIdx.x * 8 + wl;
    if (d >= N_NODES) return;

    ull wp0[16], wp1[16];
#pragma unroll
    for (int kp = 0; kp < 16; kp++) wp0[kp] = g_Wep[kp * 48 + lane];
#pragma unroll
    for (int kp = 0; kp < 16; kp++)
        wp1[kp] = (lane < 16) ? g_Wep[kp * 48 + 32 + lane] : 0ull;
    const float bia0 = be[lane];
    const float bia1 = (lane < 16) ? be[32 + lane] : 0.0f;

    float* hrow = (float*)g_h + (size_t)d * 96;
    // copy left half (nfeat)
    hrow[lane] = nfeat[d * 48 + lane];
    if (lane < 16) hrow[32 + lane] = nfeat[d * 48 + 32 + lane];

    __shared__ __align__(16) float se[8][32];

    const unsigned beg = g_off[d];
    const unsigned deg = g_cnt[d];
    float acc0 = 0.0f, acc1 = 0.0f;
    for (unsigned i = 0; i < deg; i++) {
        int e = g_pe[beg + i];
        int s = g_ps[beg + i];
        se[wl][lane] = efeat[(size_t)e * 32 + lane];
        __syncwarp();
        ull a0 = 0ull, a1 = 0ull;
#pragma unroll
        for (int kp = 0; kp < 16; kp++) {
            ull a2 = *(const ull*)&se[wl][2 * kp];
            a0 = ffma2(a2, wp0[kp], a0);
            a1 = ffma2(a2, wp1[kp], a1);
        }
        __syncwarp();
        float2 p0 = u2f(a0);
        float r0 = fmaxf(p0.x + p0.y + bia0, 0.0f);
        acc0 = fmaf(r0, nfeat[s * 48 + lane], acc0);
        if (lane < 16) {
            float2 p1 = u2f(a1);
            float r1 = fmaxf(p1.x + p1.y + bia1, 0.0f);
            acc1 = fmaf(r1, nfeat[s * 48 + 32 + lane], acc1);
        }
    }
    float iv = __fdividef(1.0f, fmaxf((float)deg, 1.0f));
    hrow[48 + lane] = acc0 * iv;
    if (lane < 16) hrow[80 + lane] = acc1 * iv;
}

// ---------------- stage B: hn1[d] = mean(h[src]) (96f, warp/node) ----------------
__global__ __launch_bounds__(256) void k_dstB() {
    const int lane = threadIdx.x & 31;
    const int d = blockIdx.x * 8 + (threadIdx.x >> 5);
    if (d >= N_NODES) return;
    const unsigned beg = g_off[d];
    const unsigned deg = g_cnt[d];
    const float* hf = (const float*)g_h;
    float a0 = 0.f, a1 = 0.f, a2 = 0.f;
    unsigned i = 0;
    for (; i + 2 <= deg; i += 2) {
        int s0 = g_ps[beg + i];
        int s1 = g_ps[beg + i + 1];
        const float* r0 = hf + (size_t)s0 * 96;
        const float* r1 = hf + (size_t)s1 * 96;
        float x0 = r0[lane], x1 = r0[32 + lane], x2 = r0[64 + lane];
        float y0 = r1[lane], y1 = r1[32 + lane], y2 = r1[64 + lane];
        a0 += x0 + y0;
        a1 += x1 + y1;
        a2 += x2 + y2;
    }
    if (i < deg) {
        const float* r0 = hf + (size_t)g_ps[beg + i] * 96;
        a0 += r0[lane];
        a1 += r0[32 + lane];
        a2 += r0[64 + lane];
    }
    float iv = __fdividef(1.0f, fmaxf((float)deg, 1.0f));
    float* o = (float*)g_hn1 + (size_t)d * 96;
    o[lane] = a0 * iv;
    o[32 + lane] = a1 * iv;
    o[64 + lane] = a2 * iv;
}

// ---------------- GEMM1: h1 = relu(h@W1s + hn1@W1n + b1), packed f32x2 ----------------
__global__ __launch_bounds__(128) void k_gemm1(const float* __restrict__ b1) {
    __shared__ __align__(16) float As[32][192];
    const int tid = threadIdx.x;
    const int node0 = blockIdx.x * 32;
    for (int i = tid; i < 32 * 48; i += 128) {
        int n = i / 48, kq = i % 48;
        int node = node0 + n;
        float4 v = (kq < 24) ? g_h[node * 24 + kq] : g_hn1[node * 24 + (kq - 24)];
        ((float4*)As[n])[kq] = v;
    }
    __syncthreads();

    const int lane = tid & 31;
    const int nb = (tid >> 5) * 8;
    const int c0 = lane * 4;
    ull acc[8][4];
#pragma unroll
    for (int n = 0; n < 8; n++)
#pragma unroll
        for (int j = 0; j < 4; j++) acc[n][j] = 0ull;

    for (int kq = 0; kq < 48; kq++) {
        const int kpA = 2 * kq, kpB = 2 * kq + 1;
        ulonglong2 wA0 = *(const ulonglong2*)&g_W1p[kpA * 128 + c0];
        ulonglong2 wA1 = *(const ulonglong2*)&g_W1p[kpA * 128 + c0 + 2];
        ulonglong2 wB0 = *(const ulonglong2*)&g_W1p[kpB * 128 + c0];
        ulonglong2 wB1 = *(const ulonglong2*)&g_W1p[kpB * 128 + c0 + 2];
#pragma unroll
        for (int n = 0; n < 8; n++) {
            ulonglong2 a = *(const ulonglong2*)&As[nb + n][4 * kq];
            acc[n][0] = ffma2(a.x, wA0.x, acc[n][0]);
            acc[n][1] = ffma2(a.x, wA0.y, acc[n][1]);
            acc[n][2] = ffma2(a.x, wA1.x, acc[n][2]);
            acc[n][3] = ffma2(a.x, wA1.y, acc[n][3]);
            acc[n][0] = ffma2(a.y, wB0.x, acc[n][0]);
            acc[n][1] = ffma2(a.y, wB0.y, acc[n][1]);
            acc[n][2] = ffma2(a.y, wB1.x, acc[n][2]);
            acc[n][3] = ffma2(a.y, wB1.y, acc[n][3]);
        }
    }

    float4 bb = *(const float4*)&b1[c0];
#pragma unroll
    for (int n = 0; n < 8; n++) {
        float2 p0 = u2f(acc[n][0]), p1 = u2f(acc[n][1]);
        float2 p2 = u2f(acc[n][2]), p3 = u2f(acc[n][3]);
        float4 r;
        r.x = fmaxf(p0.x + p0.y + bb.x, 0.0f);
        r.y = fmaxf(p1.x + p1.y + bb.y, 0.0f);
        r.z = fmaxf(p2.x + p2.y + bb.z, 0.0f);
        r.w = fmaxf(p3.x + p3.y + bb.w, 0.0f);
        g_h1[(node0 + nb + n) * 32 + lane] = r;
    }
}

// ---------------- GEMM-Y: y = h1 @ W2n (projection push-down) ----------------
__global__ __launch_bounds__(64) void k_gemmy() {
    __shared__ __align__(16) float As[32][128];
    const int tid = threadIdx.x;
    const int node0 = blockIdx.x * 32;
    for (int i = tid; i < 32 * 32; i += 64) {
        int n = i / 32, kq = i % 32;
        ((float4*)As[n])[kq] = g_h1[(node0 + n) * 32 + kq];
    }
    __syncthreads();

    const int lane = tid & 31;
    const int cg = lane & 15;
    const int c0 = cg * 4;
    const int nb = (tid >> 5) * 16 + (lane >> 4) * 8;
    ull acc[8][4];
#pragma unroll
    for (int n = 0; n < 8; n++)
#pragma unroll
        for (int j = 0; j < 4; j++) acc[n][j] = 0ull;

    for (int kq = 0; kq < 32; kq++) {
        const int kpA = 2 * kq, kpB = 2 * kq + 1;
        ulonglong2 wA0 = *(const ulonglong2*)&g_W2np[kpA * 64 + c0];
        ulonglong2 wA1 = *(const ulonglong2*)&g_W2np[kpA * 64 + c0 + 2];
        ulonglong2 wB0 = *(const ulonglong2*)&g_W2np[kpB * 64 + c0];
        ulonglong2 wB1 = *(const ulonglong2*)&g_W2np[kpB * 64 + c0 + 2];
#pragma unroll
        for (int n = 0; n < 8; n++) {
            ulonglong2 a = *(const ulonglong2*)&As[nb + n][4 * kq];
            acc[n][0] = ffma2(a.x, wA0.x, acc[n][0]);
            acc[n][1] = ffma2(a.x, wA0.y, acc[n][1]);
            acc[n][2] = ffma2(a.x, wA1.x, acc[n][2]);
            acc[n][3] = ffma2(a.x, wA1.y, acc[n][3]);
            acc[n][0] = ffma2(a.y, wB0.x, acc[n][0]);
            acc[n][1] = ffma2(a.y, wB0.y, acc[n][1]);
            acc[n][2] = ffma2(a.y, wB1.x, acc[n][2]);
            acc[n][3] = ffma2(a.y, wB1.y, acc[n][3]);
        }
    }
#pragma unroll
    for (int n = 0; n < 8; n++) {
        float2 p0 = u2f(acc[n][0]), p1 = u2f(acc[n][1]);
        float2 p2 = u2f(acc[n][2]), p3 = u2f(acc[n][3]);
        float4 r;
        r.x = p0.x + p0.y;
        r.y = p1.x + p1.y;
        r.z = p2.x + p2.y;
        r.w = p3.x + p3.y;
        g_y[(node0 + nb + n) * 16 + cg] = r;
    }
}

// ---------------- stage C: hn2y[d] = mean(y[src]) (64f, warp/node) ----------------
__global__ __launch_bounds__(256) void k_dstC() {
    const int lane = threadIdx.x & 31;
    const int d = blockIdx.x * 8 + (threadIdx.x >> 5);
    if (d >= N_NODES) return;
    const unsigned beg = g_off[d];
    const unsigned deg = g_cnt[d];
    const float* yf = (const float*)g_y;
    float a0 = 0.f, a1 = 0.f;
    unsigned i = 0;
    for (; i + 2 <= deg; i += 2) {
        int s0 = g_ps[beg + i];
        int s1 = g_ps[beg + i + 1];
        float2 x = *(const float2*)&yf[(size_t)s0 * 64 + 2 * lane];
        float2 y = *(const float2*)&yf[(size_t)s1 * 64 + 2 * lane];
        a0 += x.x + y.x;
        a1 += x.y + y.y;
    }
    if (i < deg) {
        float2 x = *(const float2*)&yf[(size_t)g_ps[beg + i] * 64 + 2 * lane];
        a0 += x.x;
        a1 += x.y;
    }
    float iv = __fdividef(1.0f, fmaxf((float)deg, 1.0f));
    float2* o = (float2*)((float*)g_hn2y + (size_t)d * 64);
    o[lane] = make_float2(a0 * iv, a1 * iv);
}

// ---------------- GEMM2s: out = h1@W2s + b2 + hn2y ----------------
__global__ __launch_bounds__(64) void k_gemm2s(const float* __restrict__ b2,
                                               float* __restrict__ out) {
    __shared__ __align__(16) float As[32][128];
    const int tid = threadIdx.x;
    const int node0 = blockIdx.x * 32;
    for (int i = tid; i < 32 * 32; i += 64) {
        int n = i / 32, kq = i % 32;
        ((float4*)As[n])[kq] = g_h1[(node0 + n) * 32 + kq];
    }
    __syncthreads();

    const int lane = tid & 31;
    const int cg = lane & 15;
    const int c0 = cg * 4;
    const int nb = (tid >> 5) * 16 + (lane >> 4) * 8;
    ull acc[8][4];
#pragma unroll
    for (int n = 0; n < 8; n++)
#pragma unroll
        for (int j = 0; j < 4; j++) acc[n][j] = 0ull;

    for (int kq = 0; kq < 32; kq++) {
        const int kpA = 2 * kq, kpB = 2 * kq + 1;
        ulonglong2 wA0 = *(const ulonglong2*)&g_W2sp[kpA * 64 + c0];
        ulonglong2 wA1 = *(const ulonglong2*)&g_W2sp[kpA * 64 + c0 + 2];
        ulonglong2 wB0 = *(const ulonglong2*)&g_W2sp[kpB * 64 + c0];
        ulonglong2 wB1 = *(const ulonglong2*)&g_W2sp[kpB * 64 + c0 + 2];
#pragma unroll
        for (int n = 0; n < 8; n++) {
            ulonglong2 a = *(const ulonglong2*)&As[nb + n][4 * kq];
            acc[n][0] = ffma2(a.x, wA0.x, acc[n][0]);
            acc[n][1] = ffma2(a.x, wA0.y, acc[n][1]);
            acc[n][2] = ffma2(a.x, wA1.x, acc[n][2]);
            acc[n][3] = ffma2(a.x, wA1.y, acc[n][3]);
            acc[n][0] = ffma2(a.y, wB0.x, acc[n][0]);
            acc[n][1] = ffma2(a.y, wB0.y, acc[n][1]);
            acc[n][2] = ffma2(a.y, wB1.x, acc[n][2]);
            acc[n][3] = ffma2(a.y, wB1.y, acc[n][3]);
        }
    }

    float4 bb = *(const float4*)&b2[c0];
    float4* out4 = (float4*)out;
#pragma unroll
    for (int n = 0; n < 8; n++) {
        int node = node0 + nb + n;
        float4 hz = g_hn2y[node * 16 + cg];
        float2 p0 = u2f(acc[n][0]), p1 = u2f(acc[n][1]);
        float2 p2 = u2f(acc[n][2]), p3 = u2f(acc[n][3]);
        float4 r;
        r.x = p0.x + p0.y + bb.x + hz.x;
        r.y = p1.x + p1.y + bb.y + hz.y;
        r.z = p2.x + p2.y + bb.z + hz.z;
        r.w = p3.x + p3.y + bb.w + hz.w;
        out4[node * 16 + cg] = r;
    }
}

// ---------------- launch ----------------
extern "C" void kernel_launch(void* const* d_in, const int* in_sizes, int n_in,
                              void* d_out, int out_size) {
    const float* nfeat = (const float*)d_in[0];
    const float* efeat = (const float*)d_in[1];
    const int*   src   = (const int*)d_in[2];
    const int*   dst   = (const int*)d_in[3];
    const float* We    = (const float*)d_in[4];
    const float* be    = (const float*)d_in[5];
    const float* W1s   = (const float*)d_in[6];
    const float* W1n   = (const float*)d_in[7];
    const float* b1    = (const float*)d_in[8];
    const float* W2s   = (const float*)d_in[9];
    const float* W2n   = (const float*)d_in[10];
    const float* b2    = (const float*)d_in[11];
    float* out = (float*)d_out;

    const int prep_total = 16 * 48 + 96 * 128 + 64 * 64 + 64 * 64 + N_NODES;
    k_prep<<<(prep_total + 255) / 256, 256>>>(We, W1s, W1n, W2s, W2n);

    k_hist<<<1184, 256>>>(dst);
    k_scan1<<<NB_SCAN, 256>>>();
    k_scan2<<<1, 512>>>();
    k_scan3<<<NB_SCAN, 256>>>();
    k_scatter<<<1184, 256>>>(src, dst);

    k_dstA<<<(N_NODES + 7) / 8, 256>>>(efeat, nfeat, be);
    k_dstB<<<(N_NODES + 7) / 8, 256>>>();
    k_gemm1<<<N_NODES / 32, 128>>>(b1);
    k_gemmy<<<N_NODES / 32, 64>>>();
    k_dstC<<<(N_NODES + 7) / 8, 256>>>();
    k_gemm2s<<<N_NODES / 32, 64>>>(b2, out);
}

// round 4
// speedup vs baseline: 1.6934x; 1.2760x over previous
#include <cuda_runtime.h>
#include <cstdint>

#define N_NODES 100000
#define N_EDGES 1600000
#define IN_F   48
#define EDGE_F 32
#define HID_F  128
#define OUT_F  64

typedef unsigned long long ull;

#define SCAN_NB 391   // ceil(N_NODES/256)

// ---------------- scratch (device globals; allocation-free, .bss zero) ----------------
__device__ float4 g_h[N_NODES * 24];     // [N,96]  = [nfeat | mean-neigh0]
__device__ float4 g_hn1[N_NODES * 24];   // [N,96]  mean of h[src] per dst
__device__ float4 g_h1[N_NODES * 32];    // [N,128]
__device__ float4 g_y[N_NODES * 16];     // [N,64]  = h1 @ W2n
__device__ float4 g_hn2y[N_NODES * 16];  // [N,64]  mean of y[src] per dst
__device__ unsigned g_cnt[N_NODES];      // in-degree (zeroed at end of each run)
__device__ unsigned g_off[N_NODES + 1];  // CSR offsets
__device__ unsigned g_cur[N_NODES];      // scatter cursors
__device__ unsigned g_stat[512];         // lookback status (zeroed each run)
__device__ ull g_pse[N_EDGES];           // (src<<32 | edge) grouped by dst
__device__ int g_ps[N_EDGES];            // src grouped by dst

// packed weights: element = (W[2kp][c], W[2kp+1][c]) as f32x2 in a u64
__device__ ull g_Wep[16 * 48];
__device__ ull g_W1p[96 * 128];
__device__ ull g_W2sp[64 * 64];
__device__ ull g_W2np[64 * 64];

// ---------------- helpers ----------------
__device__ __forceinline__ ull ffma2(ull a, ull b, ull c) {
    ull d;
    asm("fma.rn.f32x2 %0, %1, %2, %3;" : "=l"(d) : "l"(a), "l"(b), "l"(c));
    return d;
}
__device__ __forceinline__ ull f2u(float x, float y) {
    ull r;
    asm("mov.b64 %0, {%1,%2};" : "=l"(r) : "f"(x), "f"(y));
    return r;
}
__device__ __forceinline__ float2 u2f(ull v) {
    float2 r;
    asm("mov.b64 {%0,%1}, %2;" : "=f"(r.x), "=f"(r.y) : "l"(v));
    return r;
}
__device__ __forceinline__ void red_u32(unsigned* p, unsigned v) {
    asm volatile("red.global.add.u32 [%0], %1;" :: "l"(p), "r"(v) : "memory");
}

// ---------------- launch 0: weight prepack + degree histogram ----------------
__global__ void k_histprep(const int* __restrict__ dst, const float* __restrict__ We,
                           const float* __restrict__ W1s, const float* __restrict__ W1n,
                           const float* __restrict__ W2s, const float* __restrict__ W2n) {
    const int T0 = 16 * 48;
    const int T1 = T0 + 96 * 128;
    const int T2 = T1 + 64 * 64;
    const int T3 = T2 + 64 * 64;
    const int tid = blockIdx.x * blockDim.x + threadIdx.x;
    const int stride = gridDim.x * blockDim.x;
    for (int i = tid; i < T3; i += stride) {
        if (i < T0) {
            int kp = i / 48, c = i % 48;
            g_Wep[i] = f2u(We[(2 * kp) * 48 + c], We[(2 * kp + 1) * 48 + c]);
        } else if (i < T1) {
            int j = i - T0, kp = j / 128, c = j % 128;
            const float* W = (kp < 48) ? W1s : W1n;
            int k0 = (kp < 48) ? 2 * kp : 2 * (kp - 48);
            g_W1p[j] = f2u(W[k0 * 128 + c], W[(k0 + 1) * 128 + c]);
        } else if (i < T2) {
            int j = i - T1, kp = j / 64, c = j % 64;
            g_W2sp[j] = f2u(W2s[(2 * kp) * 64 + c], W2s[(2 * kp + 1) * 64 + c]);
        } else {
            int j = i - T2, kp = j / 64, c = j % 64;
            g_W2np[j] = f2u(W2n[(2 * kp) * 64 + c], W2n[(2 * kp + 1) * 64 + c]);
        }
    }
    for (int e = tid; e < N_EDGES; e += stride) red_u32(&g_cnt[dst[e]], 1u);
}

// ---------------- launch 1: single-kernel exclusive scan (decoupled lookback) ----------------
__global__ __launch_bounds__(256) void k_scan() {
    __shared__ unsigned sh[256];
    __shared__ unsigned s_excl;
    const int b = blockIdx.x, t = threadIdx.x;
    const int i = b * 256 + t;
    unsigned v = (i < N_NODES) ? g_cnt[i] : 0u;
    sh[t] = v;
    __syncthreads();
#pragma unroll
    for (int ofs = 1; ofs < 256; ofs <<= 1) {
        unsigned x = (t >= ofs) ? sh[t - ofs] : 0u;
        __syncthreads();
        sh[t] += x;
        __syncthreads();
    }
    const unsigned incl = sh[t];
    const unsigned T = sh[255];
    if (t == 0) {
        if (b > 0) atomicExch(&g_stat[b], 0x40000000u | T);  // AGG
        unsigned excl = 0;
        if (b > 0) {
            int p = b - 1;
            while (true) {
                unsigned s;
                do { s = *(volatile unsigned*)&g_stat[p]; } while (s < 0x40000000u);
                excl += s & 0x3FFFFFFFu;
                if (s >= 0x80000000u) break;  // PREFIX
                p--;
            }
        }
        atomicExch(&g_stat[b], 0x80000000u | (excl + T));
        s_excl = excl;
    }
    __syncthreads();
    if (i < N_NODES) {
        unsigned o = s_excl + incl - v;
        g_off[i] = o;
        g_cur[i] = o;
        g_cnt[i] = 0u;  // re-zero for next launch
    }
    if (i == 0) g_off[N_NODES] = N_EDGES;
}

// ---------------- launch 2: scatter edges into CSR order (+ rezero g_stat) ----------------
__global__ void k_scatter(const int* __restrict__ src, const int* __restrict__ dst) {
    const int tid = blockIdx.x * blockDim.x + threadIdx.x;
    if (tid < 512) g_stat[tid] = 0u;
    const int stride = gridDim.x * blockDim.x;
    for (int e = tid; e < N_EDGES; e += stride) {
        int d = dst[e];
        unsigned pos = atomicAdd(&g_cur[d], 1u);
        int s = src[e];
        g_pse[pos] = ((ull)(unsigned)s << 32) | (unsigned)e;
        g_ps[pos] = s;
    }
}

// ---------------- launch 3: per-dst edge-MLP reduction (pipelined, 2 edges/iter) ----------------
__global__ __launch_bounds__(256) void k_dstA(
    const float* __restrict__ efeat, const float* __restrict__ nfeat,
    const float* __restrict__ be) {
    const int lane = threadIdx.x & 31;
    const int wl = threadIdx.x >> 5;
    const int d = blockIdx.x * 8 + wl;
    if (d >= N_NODES) return;

    ull wp0[16], wp1[16];
#pragma unroll
    for (int kp = 0; kp < 16; kp++) wp0[kp] = g_Wep[kp * 48 + lane];
#pragma unroll
    for (int kp = 0; kp < 16; kp++)
        wp1[kp] = (lane < 16) ? g_Wep[kp * 48 + 32 + lane] : 0ull;
    const float bia0 = be[lane];
    const float bia1 = (lane < 16) ? be[32 + lane] : 0.0f;

    float* hrow = (float*)g_h + (size_t)d * 96;
    hrow[lane] = nfeat[d * 48 + lane];
    if (lane < 16) hrow[32 + lane] = nfeat[d * 48 + 32 + lane];

    __shared__ __align__(16) float se[8][2][64];

    const unsigned beg = g_off[d];
    const unsigned end = g_off[d + 1];
    const unsigned deg = end - beg;
    float acc0 = 0.0f, acc1 = 0.0f;
    unsigned i = beg;
    int buf = 0;
    for (; i + 2 <= end; i += 2, buf ^= 1) {
        ull p0 = g_pse[i], p1 = g_pse[i + 1];
        int e0 = (int)(unsigned)p0, s0 = (int)(p0 >> 32);
        int e1 = (int)(unsigned)p1, s1 = (int)(p1 >> 32);
        float nf0 = nfeat[s0 * 48 + lane];
        float nf1 = nfeat[s1 * 48 + lane];
        float nf0b = 0.f, nf1b = 0.f;
        if (lane < 16) {
            nf0b = nfeat[s0 * 48 + 32 + lane];
            nf1b = nfeat[s1 * 48 + 32 + lane];
        }
        se[wl][buf][lane] = efeat[(size_t)e0 * 32 + lane];
        se[wl][buf][32 + lane] = efeat[(size_t)e1 * 32 + lane];
        __syncwarp();
        ull a0 = 0ull, a1 = 0ull, b0 = 0ull, b1 = 0ull;
#pragma unroll
        for (int kp = 0; kp < 16; kp++) {
            ull x0 = *(const ull*)&se[wl][buf][2 * kp];
            ull x1 = *(const ull*)&se[wl][buf][32 + 2 * kp];
            a0 = ffma2(x0, wp0[kp], a0);
            b0 = ffma2(x1, wp0[kp], b0);
            a1 = ffma2(x0, wp1[kp], a1);
            b1 = ffma2(x1, wp1[kp], b1);
        }
        float2 pa = u2f(a0);
        float r0 = fmaxf(pa.x + pa.y + bia0, 0.0f);
        acc0 = fmaf(r0, nf0, acc0);
        float2 pb = u2f(b0);
        float r1 = fmaxf(pb.x + pb.y + bia0, 0.0f);
        acc0 = fmaf(r1, nf1, acc0);
        if (lane < 16) {
            float2 qa = u2f(a1);
            acc1 = fmaf(fmaxf(qa.x + qa.y + bia1, 0.0f), nf0b, acc1);
            float2 qb = u2f(b1);
            acc1 = fmaf(fmaxf(qb.x + qb.y + bia1, 0.0f), nf1b, acc1);
        }
    }
    if (i < end) {
        ull p0 = g_pse[i];
        int e0 = (int)(unsigned)p0, s0 = (int)(p0 >> 32);
        float nf0 = nfeat[s0 * 48 + lane];
        float nf0b = (lane < 16) ? nfeat[s0 * 48 + 32 + lane] : 0.f;
        se[wl][buf][lane] = efeat[(size_t)e0 * 32 + lane];
        __syncwarp();
        ull a0 = 0ull, a1 = 0ull;
#pragma unroll
        for (int kp = 0; kp < 16; kp++) {
            ull x0 = *(const ull*)&se[wl][buf][2 * kp];
            a0 = ffma2(x0, wp0[kp], a0);
            a1 = ffma2(x0, wp1[kp], a1);
        }
        float2 pa = u2f(a0);
        acc0 = fmaf(fmaxf(pa.x + pa.y + bia0, 0.0f), nf0, acc0);
        if (lane < 16) {
            float2 qa = u2f(a1);
            acc1 = fmaf(fmaxf(qa.x + qa.y + bia1, 0.0f), nf0b, acc1);
        }
    }
    float iv = __fdividef(1.0f, fmaxf((float)deg, 1.0f));
    hrow[48 + lane] = acc0 * iv;
    if (lane < 16) hrow[80 + lane] = acc1 * iv;
}

// ---------------- launch 4: hn1[d] = mean(h[src]) (96f, warp/node, unroll 4) ----------------
__global__ __launch_bounds__(256) void k_dstB() {
    const int lane = threadIdx.x & 31;
    const int d = blockIdx.x * 8 + (threadIdx.x >> 5);
    if (d >= N_NODES) return;
    const unsigned beg = g_off[d];
    const unsigned end = g_off[d + 1];
    const unsigned deg = end - beg;
    const float* hf = (const float*)g_h;
    float a0 = 0.f, a1 = 0.f, a2 = 0.f;
    unsigned i = beg;
    for (; i + 4 <= end; i += 4) {
        int s0 = g_ps[i], s1 = g_ps[i + 1], s2 = g_ps[i + 2], s3 = g_ps[i + 3];
        const float* r0 = hf + (size_t)s0 * 96;
        const float* r1 = hf + (size_t)s1 * 96;
        const float* r2 = hf + (size_t)s2 * 96;
        const float* r3 = hf + (size_t)s3 * 96;
        float x00 = r0[lane], x01 = r0[32 + lane], x02 = r0[64 + lane];
        float x10 = r1[lane], x11 = r1[32 + lane], x12 = r1[64 + lane];
        float x20 = r2[lane], x21 = r2[32 + lane], x22 = r2[64 + lane];
        float x30 = r3[lane], x31 = r3[32 + lane], x32 = r3[64 + lane];
        a0 += (x00 + x10) + (x20 + x30);
        a1 += (x01 + x11) + (x21 + x31);
        a2 += (x02 + x12) + (x22 + x32);
    }
    for (; i < end; i++) {
        const float* r0 = hf + (size_t)g_ps[i] * 96;
        a0 += r0[lane];
        a1 += r0[32 + lane];
        a2 += r0[64 + lane];
    }
    float iv = __fdividef(1.0f, fmaxf((float)deg, 1.0f));
    float* o = (float*)g_hn1 + (size_t)d * 96;
    o[lane] = a0 * iv;
    o[32 + lane] = a1 * iv;
    o[64 + lane] = a2 * iv;
}

// ---------------- launch 5: GEMM1 + fused y-projection ----------------
// h1 = relu(h@W1s + hn1@W1n + b1);  y = h1 @ W2n
__global__ __launch_bounds__(128) void k_gemm1y(const float* __restrict__ b1) {
    __shared__ __align__(16) float As[32][192];
    __shared__ __align__(16) float Hs[32][128];
    const int tid = threadIdx.x;
    const int node0 = blockIdx.x * 32;
    for (int i = tid; i < 32 * 48; i += 128) {
        int n = i / 48, kq = i % 48;
        int node = node0 + n;
        float4 v = (kq < 24) ? g_h[node * 24 + kq] : g_hn1[node * 24 + (kq - 24)];
        ((float4*)As[n])[kq] = v;
    }
    __syncthreads();

    const int lane = tid & 31;
    const int nb = (tid >> 5) * 8;
    const int c0 = lane * 4;
    {
        ull acc[8][4];
#pragma unroll
        for (int n = 0; n < 8; n++)
#pragma unroll
            for (int j = 0; j < 4; j++) acc[n][j] = 0ull;

        for (int kq = 0; kq < 48; kq++) {
            const int kpA = 2 * kq, kpB = 2 * kq + 1;
            ulonglong2 wA0 = *(const ulonglong2*)&g_W1p[kpA * 128 + c0];
            ulonglong2 wA1 = *(const ulonglong2*)&g_W1p[kpA * 128 + c0 + 2];
            ulonglong2 wB0 = *(const ulonglong2*)&g_W1p[kpB * 128 + c0];
            ulonglong2 wB1 = *(const ulonglong2*)&g_W1p[kpB * 128 + c0 + 2];
#pragma unroll
            for (int n = 0; n < 8; n++) {
                ulonglong2 a = *(const ulonglong2*)&As[nb + n][4 * kq];
                acc[n][0] = ffma2(a.x, wA0.x, acc[n][0]);
                acc[n][1] = ffma2(a.x, wA0.y, acc[n][1]);
                acc[n][2] = ffma2(a.x, wA1.x, acc[n][2]);
                acc[n][3] = ffma2(a.x, wA1.y, acc[n][3]);
                acc[n][0] = ffma2(a.y, wB0.x, acc[n][0]);
                acc[n][1] = ffma2(a.y, wB0.y, acc[n][1]);
                acc[n][2] = ffma2(a.y, wB1.x, acc[n][2]);
                acc[n][3] = ffma2(a.y, wB1.y, acc[n][3]);
            }
        }

        float4 bb = *(const float4*)&b1[c0];
#pragma unroll
        for (int n = 0; n < 8; n++) {
            float2 p0 = u2f(acc[n][0]), p1 = u2f(acc[n][1]);
            float2 p2 = u2f(acc[n][2]), p3 = u2f(acc[n][3]);
            float4 r;
            r.x = fmaxf(p0.x + p0.y + bb.x, 0.0f);
            r.y = fmaxf(p1.x + p1.y + bb.y, 0.0f);
            r.z = fmaxf(p2.x + p2.y + bb.z, 0.0f);
            r.w = fmaxf(p3.x + p3.y + bb.w, 0.0f);
            g_h1[(node0 + nb + n) * 32 + lane] = r;
            ((float4*)Hs[nb + n])[lane] = r;
        }
    }
    __syncthreads();

    // y phase: 4 nodes per half-warp, 16 col-groups
    const int cg = lane & 15;
    const int c1 = cg * 4;
    const int nb2 = (tid >> 5) * 8 + (lane >> 4) * 4;
    ull acc[4][4];
#pragma unroll
    for (int n = 0; n < 4; n++)
#pragma unroll
        for (int j = 0; j < 4; j++) acc[n][j] = 0ull;

    for (int kq = 0; kq < 32; kq++) {
        const int kpA = 2 * kq, kpB = 2 * kq + 1;
        ulonglong2 wA0 = *(const ulonglong2*)&g_W2np[kpA * 64 + c1];
        ulonglong2 wA1 = *(const ulonglong2*)&g_W2np[kpA * 64 + c1 + 2];
        ulonglong2 wB0 = *(const ulonglong2*)&g_W2np[kpB * 64 + c1];
        ulonglong2 wB1 = *(const ulonglong2*)&g_W2np[kpB * 64 + c1 + 2];
#pragma unroll
        for (int n = 0; n < 4; n++) {
            ulonglong2 a = *(const ulonglong2*)&Hs[nb2 + n][4 * kq];
            acc[n][0] = ffma2(a.x, wA0.x, acc[n][0]);
            acc[n][1] = ffma2(a.x, wA0.y, acc[n][1]);
            acc[n][2] = ffma2(a.x, wA1.x, acc[n][2]);
            acc[n][3] = ffma2(a.x, wA1.y, acc[n][3]);
            acc[n][0] = ffma2(a.y, wB0.x, acc[n][0]);
            acc[n][1] = ffma2(a.y, wB0.y, acc[n][1]);
            acc[n][2] = ffma2(a.y, wB1.x, acc[n][2]);
            acc[n][3] = ffma2(a.y, wB1.y, acc[n][3]);
        }
    }
#pragma unroll
    for (int n = 0; n < 4; n++) {
        float2 p0 = u2f(acc[n][0]), p1 = u2f(acc[n][1]);
        float2 p2 = u2f(acc[n][2]), p3 = u2f(acc[n][3]);
        float4 r;
        r.x = p0.x + p0.y;
        r.y = p1.x + p1.y;
        r.z = p2.x + p2.y;
        r.w = p3.x + p3.y;
        g_y[(node0 + nb2 + n) * 16 + cg] = r;
    }
}

// ---------------- launch 6: hn2y[d] = mean(y[src]) (64f, warp/node, unroll 4) ----------------
__global__ __launch_bounds__(256) void k_dstC() {
    const int lane = threadIdx.x & 31;
    const int d = blockIdx.x * 8 + (threadIdx.x >> 5);
    if (d >= N_NODES) return;
    const unsigned beg = g_off[d];
    const unsigned end = g_off[d + 1];
    const unsigned deg = end - beg;
    const float* yf = (const float*)g_y;
    float a0 = 0.f, a1 = 0.f;
    unsigned i = beg;
    for (; i + 4 <= end; i += 4) {
        int s0 = g_ps[i], s1 = g_ps[i + 1], s2 = g_ps[i + 2], s3 = g_ps[i + 3];
        float2 x0 = *(const float2*)&yf[(size_t)s0 * 64 + 2 * lane];
        float2 x1 = *(const float2*)&yf[(size_t)s1 * 64 + 2 * lane];
        float2 x2 = *(const float2*)&yf[(size_t)s2 * 64 + 2 * lane];
        float2 x3 = *(const float2*)&yf[(size_t)s3 * 64 + 2 * lane];
        a0 += (x0.x + x1.x) + (x2.x + x3.x);
        a1 += (x0.y + x1.y) + (x2.y + x3.y);
    }
    for (; i < end; i++) {
        float2 x = *(const float2*)&yf[(size_t)g_ps[i] * 64 + 2 * lane];
        a0 += x.x;
        a1 += x.y;
    }
    float iv = __fdividef(1.0f, fmaxf((float)deg, 1.0f));
    float2* o = (float2*)((float*)g_hn2y + (size_t)d * 64);
    o[lane] = make_float2(a0 * iv, a1 * iv);
}

// ---------------- launch 7: out = h1@W2s + b2 + hn2y ----------------
__global__ __launch_bounds__(64) void k_gemm2s(const float* __restrict__ b2,
                                               float* __restrict__ out) {
    __shared__ __align__(16) float As[32][128];
    const int tid = threadIdx.x;
    const int node0 = blockIdx.x * 32;
    for (int i = tid; i < 32 * 32; i += 64) {
        int n = i / 32, kq = i % 32;
        ((float4*)As[n])[kq] = g_h1[(node0 + n) * 32 + kq];
    }
    __syncthreads();

    const int lane = tid & 31;
    const int cg = lane & 15;
    const int c0 = cg * 4;
    const int nb = (tid >> 5) * 16 + (lane >> 4) * 8;
    ull acc[8][4];
#pragma unroll
    for (int n = 0; n < 8; n++)
#pragma unroll
        for (int j = 0; j < 4; j++) acc[n][j] = 0ull;

    for (int kq = 0; kq < 32; kq++) {
        const int kpA = 2 * kq, kpB = 2 * kq + 1;
        ulonglong2 wA0 = *(const ulonglong2*)&g_W2sp[kpA * 64 + c0];
        ulonglong2 wA1 = *(const ulonglong2*)&g_W2sp[kpA * 64 + c0 + 2];
        ulonglong2 wB0 = *(const ulonglong2*)&g_W2sp[kpB * 64 + c0];
        ulonglong2 wB1 = *(const ulonglong2*)&g_W2sp[kpB * 64 + c0 + 2];
#pragma unroll
        for (int n = 0; n < 8; n++) {
            ulonglong2 a = *(const ulonglong2*)&As[nb + n][4 * kq];
            acc[n][0] = ffma2(a.x, wA0.x, acc[n][0]);
            acc[n][1] = ffma2(a.x, wA0.y, acc[n][1]);
            acc[n][2] = ffma2(a.x, wA1.x, acc[n][2]);
            acc[n][3] = ffma2(a.x, wA1.y, acc[n][3]);
            acc[n][0] = ffma2(a.y, wB0.x, acc[n][0]);
            acc[n][1] = ffma2(a.y, wB0.y, acc[n][1]);
            acc[n][2] = ffma2(a.y, wB1.x, acc[n][2]);
            acc[n][3] = ffma2(a.y, wB1.y, acc[n][3]);
        }
    }

    float4 bb = *(const float4*)&b2[c0];
    float4* out4 = (float4*)out;
#pragma unroll
    for (int n = 0; n < 8; n++) {
        int node = node0 + nb + n;
        float4 hz = g_hn2y[node * 16 + cg];
        float2 p0 = u2f(acc[n][0]), p1 = u2f(acc[n][1]);
        float2 p2 = u2f(acc[n][2]), p3 = u2f(acc[n][3]);
        float4 r;
        r.x = p0.x + p0.y + bb.x + hz.x;
        r.y = p1.x + p1.y + bb.y + hz.y;
        r.z = p2.x + p2.y + bb.z + hz.z;
        r.w = p3.x + p3.y + bb.w + hz.w;
        out4[node * 16 + cg] = r;
    }
}

// ---------------- launch ----------------
extern "C" void kernel_launch(void* const* d_in, const int* in_sizes, int n_in,
                              void* d_out, int out_size) {
    const float* nfeat = (const float*)d_in[0];
    const float* efeat = (const float*)d_in[1];
    const int*   src   = (const int*)d_in[2];
    const int*   dst   = (const int*)d_in[3];
    const float* We    = (const float*)d_in[4];
    const float* be    = (const float*)d_in[5];
    const float* W1s   = (const float*)d_in[6];
    const float* W1n   = (const float*)d_in[7];
    const float* b1    = (const float*)d_in[8];
    const float* W2s   = (const float*)d_in[9];
    const float* W2n   = (const float*)d_in[10];
    const float* b2    = (const float*)d_in[11];
    float* out = (float*)d_out;

    k_histprep<<<1184, 256>>>(dst, We, W1s, W1n, W2s, W2n);   // 0
    k_scan<<<SCAN_NB, 256>>>();                               // 1
    k_scatter<<<1184, 256>>>(src, dst);                       // 2
    k_dstA<<<(N_NODES + 7) / 8, 256>>>(efeat, nfeat, be);     // 3  <- profiled
    k_dstB<<<(N_NODES + 7) / 8, 256>>>();                     // 4
    k_gemm1y<<<N_NODES / 32, 128>>>(b1);                      // 5
    k_dstC<<<(N_NODES + 7) / 8, 256>>>();                     // 6
    k_gemm2s<<<N_NODES / 32, 64>>>(b2, out);                  // 7
}